// round 1
// baseline (speedup 1.0000x reference)
#include <cuda_runtime.h>
#include <cuda_bf16.h>

// BSplineACTF: per-channel cubic B-spline activation, uniform knots.
// x:[16,256,256,32] f32, grid:[12] f32 (uniform linspace -2.2..2.2), W:[32,8] f32.
// out[...,c] = sum_k N_k(x) * W[c][k]  (cubic Cox-de Boor, 8 bases).
//
// Optimization: uniform knots => only 4 bases nonzero per interval j (j=0..10).
// Pre-collapse per (c,j) into a single cubic in local coord t:
//   p_{c,j}(t) = c0 + c1 t + c2 t^2 + c3 t^3
// with
//   c0 = (w1 + 4 w2 + w3)/6
//   c1 = (w1 - w3)/2
//   c2 = (w1 - 2 w2 + w3)/2
//   c3 = (w0 - 3 w1 + 3 w2 - w3)/6
// where wm = W[c][j-m] (0 if j-m outside 0..7).
// Hot loop per element: u=(x-g0)*inv_h; j=floor(u); t=u-j; one LDS.128; Horner.

#define NTHREADS 256
#define NBLOCKS  2368   // 16 blocks/SM on 148 SMs; grid-stride amortizes smem setup

__global__ __launch_bounds__(NTHREADS) void bspline_actf_kernel(
    const float* __restrict__ x,
    const float* __restrict__ grid,
    const float* __restrict__ W,
    float* __restrict__ out,
    int n)
{
    __shared__ float4 sc[32 * 11];   // [channel][interval] cubic coeffs, stride 11

    const float g0    = grid[0];
    const float g11   = grid[11];
    const float h     = (g11 - g0) * (1.0f / 11.0f);
    const float inv_h = 1.0f / h;

    // ---- one-time per-block coefficient build (352 records) ----
    for (int idx = threadIdx.x; idx < 32 * 11; idx += NTHREADS) {
        int c = idx / 11;
        int j = idx - c * 11;
        const float* Wc = W + c * 8;
        float w0 = (j     >= 0 && j     < 8) ? __ldg(Wc + j)     : 0.0f;
        float w1 = (j - 1 >= 0 && j - 1 < 8) ? __ldg(Wc + j - 1) : 0.0f;
        float w2 = (j - 2 >= 0 && j - 2 < 8) ? __ldg(Wc + j - 2) : 0.0f;
        float w3 = (j - 3 >= 0 && j - 3 < 8) ? __ldg(Wc + j - 3) : 0.0f;
        float4 cf;
        cf.x = (w1 + 4.0f * w2 + w3) * (1.0f / 6.0f);
        cf.y = (w1 - w3) * 0.5f;
        cf.z = (w1 - 2.0f * w2 + w3) * 0.5f;
        cf.w = (w0 - 3.0f * w1 + 3.0f * w2 - w3) * (1.0f / 6.0f);
        sc[idx] = cf;
    }
    __syncthreads();

    const int gtid   = blockIdx.x * NTHREADS + threadIdx.x;
    const int stride = gridDim.x * NTHREADS;
    const int n4     = n >> 2;

    // channel of element 4*v is (4*v) & 31; since stride % 8 == 0 (in vectors),
    // each thread's channel quartet is loop-invariant.
    const int c0 = (gtid & 7) * 4;
    const float4* __restrict__ row0 = sc + (c0 + 0) * 11;
    const float4* __restrict__ row1 = sc + (c0 + 1) * 11;
    const float4* __restrict__ row2 = sc + (c0 + 2) * 11;
    const float4* __restrict__ row3 = sc + (c0 + 3) * 11;

    const float4* __restrict__ x4 = (const float4*)x;
    float4* __restrict__ o4       = (float4*)out;

    auto evalspline = [&](float xv, const float4* __restrict__ rowp) -> float {
        float u  = (xv - g0) * inv_h;
        float jf = floorf(u);
        int   j  = (int)jf;
        float t  = u - jf;
        int   jc = min(max(j, 0), 10);      // clamp for safe smem access
        float4 cf = rowp[jc];
        float r = fmaf(fmaf(fmaf(cf.w, t, cf.z), t, cf.y), t, cf.x);
        return ((unsigned)j < 11u) ? r : 0.0f;   // outside [g0, g11) -> 0
    };

    for (int v = gtid; v < n4; v += stride) {
        float4 xv = x4[v];
        float4 ov;
        ov.x = evalspline(xv.x, row0);
        ov.y = evalspline(xv.y, row1);
        ov.z = evalspline(xv.z, row2);
        ov.w = evalspline(xv.w, row3);
        o4[v] = ov;
    }

    // scalar tail (n not divisible by 4) — not hit for this shape, kept for safety
    for (int e = (n4 << 2) + gtid; e < n; e += stride) {
        int c = e & 31;
        out[e] = evalspline(x[e], sc + c * 11);
    }
}

extern "C" void kernel_launch(void* const* d_in, const int* in_sizes, int n_in,
                              void* d_out, int out_size)
{
    const float* x    = (const float*)d_in[0];
    const float* grid = (const float*)d_in[1];
    const float* W    = (const float*)d_in[2];
    float* out        = (float*)d_out;
    int n = in_sizes[0];

    int n4 = n >> 2;
    int blocks = NBLOCKS;
    int maxBlocks = (n4 + NTHREADS - 1) / NTHREADS;
    if (maxBlocks < 1) maxBlocks = 1;
    if (blocks > maxBlocks) blocks = maxBlocks;

    bspline_actf_kernel<<<blocks, NTHREADS>>>(x, grid, W, out, n);
}

// round 2
// speedup vs baseline: 1.2781x; 1.2781x over previous
#include <cuda_runtime.h>
#include <cuda_bf16.h>

// BSplineACTF: per-channel cubic B-spline activation, uniform knots.
// x:[16,256,256,32] f32, grid:[12] f32 (uniform linspace -2.2..2.2), W:[32,8] f32.
// out[...,c] = sum_k N_k(x) * W[c][k]  (cubic Cox-de Boor, 8 bases).
//
// Optimization: uniform knots => only 4 bases nonzero per interval j (j=0..10).
// Pre-collapse per (c,j) into a single cubic in local coord t:
//   p_{c,j}(t) = c0 + c1 t + c2 t^2 + c3 t^3
// with
//   c0 = (w1 + 4 w2 + w3)/6
//   c1 = (w1 - w3)/2
//   c2 = (w1 - 2 w2 + w3)/2
//   c3 = (w0 - 3 w1 + 3 w2 - w3)/6
// where wm = W[c][j-m] (0 if j-m outside 0..7).
// Hot loop per element: u=(x-g0)*inv_h; j=floor(u); t=u-j; one LDS.128; Horner.

#define NTHREADS 256
#define NBLOCKS  2368   // 16 blocks/SM on 148 SMs; grid-stride amortizes smem setup

__global__ __launch_bounds__(NTHREADS) void bspline_actf_kernel(
    const float* __restrict__ x,
    const float* __restrict__ grid,
    const float* __restrict__ W,
    float* __restrict__ out,
    int n)
{
    __shared__ float4 sc[32 * 11];   // [channel][interval] cubic coeffs, stride 11

    const float g0    = grid[0];
    const float g11   = grid[11];
    const float h     = (g11 - g0) * (1.0f / 11.0f);
    const float inv_h = 1.0f / h;

    // ---- one-time per-block coefficient build (352 records) ----
    for (int idx = threadIdx.x; idx < 32 * 11; idx += NTHREADS) {
        int c = idx / 11;
        int j = idx - c * 11;
        const float* Wc = W + c * 8;
        float w0 = (j     >= 0 && j     < 8) ? __ldg(Wc + j)     : 0.0f;
        float w1 = (j - 1 >= 0 && j - 1 < 8) ? __ldg(Wc + j - 1) : 0.0f;
        float w2 = (j - 2 >= 0 && j - 2 < 8) ? __ldg(Wc + j - 2) : 0.0f;
        float w3 = (j - 3 >= 0 && j - 3 < 8) ? __ldg(Wc + j - 3) : 0.0f;
        float4 cf;
        cf.x = (w1 + 4.0f * w2 + w3) * (1.0f / 6.0f);
        cf.y = (w1 - w3) * 0.5f;
        cf.z = (w1 - 2.0f * w2 + w3) * 0.5f;
        cf.w = (w0 - 3.0f * w1 + 3.0f * w2 - w3) * (1.0f / 6.0f);
        sc[idx] = cf;
    }
    __syncthreads();

    const int gtid   = blockIdx.x * NTHREADS + threadIdx.x;
    const int stride = gridDim.x * NTHREADS;
    const int n4     = n >> 2;

    // channel of element 4*v is (4*v) & 31; since stride % 8 == 0 (in vectors),
    // each thread's channel quartet is loop-invariant.
    const int c0 = (gtid & 7) * 4;
    const float4* __restrict__ row0 = sc + (c0 + 0) * 11;
    const float4* __restrict__ row1 = sc + (c0 + 1) * 11;
    const float4* __restrict__ row2 = sc + (c0 + 2) * 11;
    const float4* __restrict__ row3 = sc + (c0 + 3) * 11;

    const float4* __restrict__ x4 = (const float4*)x;
    float4* __restrict__ o4       = (float4*)out;

    auto evalspline = [&](float xv, const float4* __restrict__ rowp) -> float {
        float u  = (xv - g0) * inv_h;
        float jf = floorf(u);
        int   j  = (int)jf;
        float t  = u - jf;
        int   jc = min(max(j, 0), 10);      // clamp for safe smem access
        float4 cf = rowp[jc];
        float r = fmaf(fmaf(fmaf(cf.w, t, cf.z), t, cf.y), t, cf.x);
        return ((unsigned)j < 11u) ? r : 0.0f;   // outside [g0, g11) -> 0
    };

    for (int v = gtid; v < n4; v += stride) {
        float4 xv = x4[v];
        float4 ov;
        ov.x = evalspline(xv.x, row0);
        ov.y = evalspline(xv.y, row1);
        ov.z = evalspline(xv.z, row2);
        ov.w = evalspline(xv.w, row3);
        o4[v] = ov;
    }

    // scalar tail (n not divisible by 4) — not hit for this shape, kept for safety
    for (int e = (n4 << 2) + gtid; e < n; e += stride) {
        int c = e & 31;
        out[e] = evalspline(x[e], sc + c * 11);
    }
}

extern "C" void kernel_launch(void* const* d_in, const int* in_sizes, int n_in,
                              void* d_out, int out_size)
{
    const float* x    = (const float*)d_in[0];
    const float* grid = (const float*)d_in[1];
    const float* W    = (const float*)d_in[2];
    float* out        = (float*)d_out;
    int n = in_sizes[0];

    int n4 = n >> 2;
    int blocks = NBLOCKS;
    int maxBlocks = (n4 + NTHREADS - 1) / NTHREADS;
    if (maxBlocks < 1) maxBlocks = 1;
    if (blocks > maxBlocks) blocks = maxBlocks;

    bspline_actf_kernel<<<blocks, NTHREADS>>>(x, grid, W, out, n);
}

// round 3
// speedup vs baseline: 1.5147x; 1.1852x over previous
#include <cuda_runtime.h>
#include <cuda_fp16.h>

// BSplineACTF: per-channel cubic B-spline activation, uniform knots.
// x:[16,256,256,32] f32, grid:[12] f32, W:[32,8] f32 -> out f32.
//
// R2 ncu: L1tex 81.3% binding, DRAM 51.6%. 2/3 of L1 wavefronts were the
// per-element LDS.128 coeff fetch. R3: compress the collapsed cubic coeffs
// (c0,c1,c2,c3) per (channel, interval) to 4x fp16 (one LDS.64, 8B), halving
// the shared-memory wavefronts. Horner evaluation stays fp32; fp16 coeff
// quantization error ~2e-4 << 1e-3 gate.

#define NTHREADS 256
#define NBLOCKS  2368

__global__ __launch_bounds__(NTHREADS) void bspline_actf_kernel(
    const float* __restrict__ x,
    const float* __restrict__ grid,
    const float* __restrict__ W,
    float* __restrict__ out,
    int n)
{
    // [channel][interval] packed cubic coeffs: lo=(c0,c1), hi=(c2,c3) as half2.
    __shared__ uint2 sc[32 * 11];

    const float g0    = grid[0];
    const float g11   = grid[11];
    const float h     = (g11 - g0) * (1.0f / 11.0f);
    const float inv_h = 1.0f / h;

    // ---- one-time per-block coefficient build (352 records) ----
    for (int idx = threadIdx.x; idx < 32 * 11; idx += NTHREADS) {
        int c = idx / 11;
        int j = idx - c * 11;
        const float* Wc = W + c * 8;
        float w0 = (j     >= 0 && j     < 8) ? __ldg(Wc + j)     : 0.0f;
        float w1 = (j - 1 >= 0 && j - 1 < 8) ? __ldg(Wc + j - 1) : 0.0f;
        float w2 = (j - 2 >= 0 && j - 2 < 8) ? __ldg(Wc + j - 2) : 0.0f;
        float w3 = (j - 3 >= 0 && j - 3 < 8) ? __ldg(Wc + j - 3) : 0.0f;
        float c0 = (w1 + 4.0f * w2 + w3) * (1.0f / 6.0f);
        float c1 = (w1 - w3) * 0.5f;
        float c2 = (w1 - 2.0f * w2 + w3) * 0.5f;
        float c3 = (w0 - 3.0f * w1 + 3.0f * w2 - w3) * (1.0f / 6.0f);
        __half2 lo = __floats2half2_rn(c0, c1);
        __half2 hi = __floats2half2_rn(c2, c3);
        uint2 rec;
        rec.x = *reinterpret_cast<unsigned int*>(&lo);
        rec.y = *reinterpret_cast<unsigned int*>(&hi);
        sc[idx] = rec;
    }
    __syncthreads();

    const int gtid   = blockIdx.x * NTHREADS + threadIdx.x;
    const int stride = gridDim.x * NTHREADS;   // in float4 vectors; % 8 == 0
    const int n4     = n >> 2;

    // channel quartet of this thread's vectors is loop-invariant
    const int c0i = (gtid & 7) * 4;
    const uint2* __restrict__ row0 = sc + (c0i + 0) * 11;
    const uint2* __restrict__ row1 = sc + (c0i + 1) * 11;
    const uint2* __restrict__ row2 = sc + (c0i + 2) * 11;
    const uint2* __restrict__ row3 = sc + (c0i + 3) * 11;

    const float4* __restrict__ x4 = (const float4*)x;
    float4* __restrict__ o4       = (float4*)out;

    auto evalspline = [&](float xv, const uint2* __restrict__ rowp) -> float {
        float u  = (xv - g0) * inv_h;
        float jf = floorf(u);
        int   j  = (int)jf;
        float t  = u - jf;
        int   jc = min(max(j, 0), 10);
        uint2 rec = rowp[jc];                 // LDS.64
        __half2 lo = *reinterpret_cast<__half2*>(&rec.x);
        __half2 hi = *reinterpret_cast<__half2*>(&rec.y);
        float2 f01 = __half22float2(lo);
        float2 f23 = __half22float2(hi);
        float r = fmaf(fmaf(fmaf(f23.y, t, f23.x), t, f01.y), t, f01.x);
        return ((unsigned)j < 11u) ? r : 0.0f;
    };

    auto do_vec = [&](int v) {
        float4 xv = x4[v];
        float4 ov;
        ov.x = evalspline(xv.x, row0);
        ov.y = evalspline(xv.y, row1);
        ov.z = evalspline(xv.z, row2);
        ov.w = evalspline(xv.w, row3);
        o4[v] = ov;
    };

    // 2-way unrolled grid-stride loop: two independent LDG.128 in flight
    int v = gtid;
    for (; v + stride < n4; v += 2 * stride) {
        float4 xa = x4[v];
        float4 xb = x4[v + stride];
        float4 oa, ob;
        oa.x = evalspline(xa.x, row0);
        oa.y = evalspline(xa.y, row1);
        oa.z = evalspline(xa.z, row2);
        oa.w = evalspline(xa.w, row3);
        ob.x = evalspline(xb.x, row0);
        ob.y = evalspline(xb.y, row1);
        ob.z = evalspline(xb.z, row2);
        ob.w = evalspline(xb.w, row3);
        o4[v] = oa;
        o4[v + stride] = ob;
    }
    if (v < n4) do_vec(v);

    // scalar tail (n % 4) — not hit for this shape, kept for safety
    for (int e = (n4 << 2) + gtid; e < n; e += stride) {
        int c = e & 31;
        out[e] = evalspline(x[e], sc + c * 11);
    }
}

extern "C" void kernel_launch(void* const* d_in, const int* in_sizes, int n_in,
                              void* d_out, int out_size)
{
    const float* x    = (const float*)d_in[0];
    const float* grid = (const float*)d_in[1];
    const float* W    = (const float*)d_in[2];
    float* out        = (float*)d_out;
    int n = in_sizes[0];

    int n4 = n >> 2;
    int blocks = NBLOCKS;
    int maxBlocks = (n4 + NTHREADS - 1) / NTHREADS;
    if (maxBlocks < 1) maxBlocks = 1;
    if (blocks > maxBlocks) blocks = maxBlocks;

    bspline_actf_kernel<<<blocks, NTHREADS>>>(x, grid, W, out, n);
}

// round 4
// speedup vs baseline: 1.5824x; 1.0447x over previous
#include <cuda_runtime.h>
#include <cuda_fp16.h>

// BSplineACTF: per-channel cubic B-spline activation, uniform knots.
// x:[16,256,256,32] f32, grid:[12] f32, W:[32,8] f32 -> out f32.
//
// R3 ncu: DRAM 67.9%, L1 68.1%, issue 52.6% — latency-exposed, no pipe wall.
// R4: unroll x4 with front-batched LDG.128 (MLP_p1=4/thread), streaming cache
// hints (__ldcs/__stcs), fp16-packed collapsed-cubic table (LDS.64 lookup).

#define NTHREADS 256
#define NBLOCKS  2368

__global__ __launch_bounds__(NTHREADS) void bspline_actf_kernel(
    const float* __restrict__ x,
    const float* __restrict__ grid,
    const float* __restrict__ W,
    float* __restrict__ out,
    int n)
{
    // [channel][interval] packed cubic coeffs: lo=(c0,c1), hi=(c2,c3) as half2.
    __shared__ uint2 sc[32 * 11];

    const float g0    = grid[0];
    const float g11   = grid[11];
    const float h     = (g11 - g0) * (1.0f / 11.0f);
    const float inv_h = 1.0f / h;

    // ---- one-time per-block coefficient build (352 records) ----
    for (int idx = threadIdx.x; idx < 32 * 11; idx += NTHREADS) {
        int c = idx / 11;
        int j = idx - c * 11;
        const float* Wc = W + c * 8;
        float w0 = (j     >= 0 && j     < 8) ? __ldg(Wc + j)     : 0.0f;
        float w1 = (j - 1 >= 0 && j - 1 < 8) ? __ldg(Wc + j - 1) : 0.0f;
        float w2 = (j - 2 >= 0 && j - 2 < 8) ? __ldg(Wc + j - 2) : 0.0f;
        float w3 = (j - 3 >= 0 && j - 3 < 8) ? __ldg(Wc + j - 3) : 0.0f;
        float c0 = (w1 + 4.0f * w2 + w3) * (1.0f / 6.0f);
        float c1 = (w1 - w3) * 0.5f;
        float c2 = (w1 - 2.0f * w2 + w3) * 0.5f;
        float c3 = (w0 - 3.0f * w1 + 3.0f * w2 - w3) * (1.0f / 6.0f);
        __half2 lo = __floats2half2_rn(c0, c1);
        __half2 hi = __floats2half2_rn(c2, c3);
        uint2 rec;
        rec.x = *reinterpret_cast<unsigned int*>(&lo);
        rec.y = *reinterpret_cast<unsigned int*>(&hi);
        sc[idx] = rec;
    }
    __syncthreads();

    const int gtid   = blockIdx.x * NTHREADS + threadIdx.x;
    const int stride = gridDim.x * NTHREADS;   // in float4 vectors; % 8 == 0
    const int n4     = n >> 2;

    // channel quartet of this thread's vectors is loop-invariant
    const int c0i = (gtid & 7) * 4;
    const uint2* __restrict__ row0 = sc + (c0i + 0) * 11;
    const uint2* __restrict__ row1 = sc + (c0i + 1) * 11;
    const uint2* __restrict__ row2 = sc + (c0i + 2) * 11;
    const uint2* __restrict__ row3 = sc + (c0i + 3) * 11;

    const float4* __restrict__ x4 = (const float4*)x;
    float4* __restrict__ o4       = (float4*)out;

    auto evalspline = [&](float xv, const uint2* __restrict__ rowp) -> float {
        float u  = (xv - g0) * inv_h;
        float jf = floorf(u);
        int   j  = (int)jf;
        float t  = u - jf;
        int   jc = min(max(j, 0), 10);
        uint2 rec = rowp[jc];                 // LDS.64
        __half2 lo = *reinterpret_cast<__half2*>(&rec.x);
        __half2 hi = *reinterpret_cast<__half2*>(&rec.y);
        float2 f01 = __half22float2(lo);
        float2 f23 = __half22float2(hi);
        float r = fmaf(fmaf(fmaf(f23.y, t, f23.x), t, f01.y), t, f01.x);
        return ((unsigned)j < 11u) ? r : 0.0f;
    };

    auto eval_vec = [&](float4 xv) -> float4 {
        float4 ov;
        ov.x = evalspline(xv.x, row0);
        ov.y = evalspline(xv.y, row1);
        ov.z = evalspline(xv.z, row2);
        ov.w = evalspline(xv.w, row3);
        return ov;
    };

    // 4-way unrolled grid-stride loop: 4 independent LDG.128 front-batched.
    int v = gtid;
    for (; v + 3 * stride < n4; v += 4 * stride) {
        float4 xa = __ldcs(&x4[v]);
        float4 xb = __ldcs(&x4[v + stride]);
        float4 xc = __ldcs(&x4[v + 2 * stride]);
        float4 xd = __ldcs(&x4[v + 3 * stride]);
        float4 oa = eval_vec(xa);
        float4 ob = eval_vec(xb);
        float4 oc = eval_vec(xc);
        float4 od = eval_vec(xd);
        __stcs(&o4[v],              oa);
        __stcs(&o4[v + stride],     ob);
        __stcs(&o4[v + 2 * stride], oc);
        __stcs(&o4[v + 3 * stride], od);
    }
    for (; v < n4; v += stride) {
        float4 xv = __ldcs(&x4[v]);
        float4 ov = eval_vec(xv);
        __stcs(&o4[v], ov);
    }

    // scalar tail (n % 4) — not hit for this shape, kept for safety
    for (int e = (n4 << 2) + gtid; e < n; e += stride) {
        int c = e & 31;
        out[e] = evalspline(x[e], sc + c * 11);
    }
}

extern "C" void kernel_launch(void* const* d_in, const int* in_sizes, int n_in,
                              void* d_out, int out_size)
{
    const float* x    = (const float*)d_in[0];
    const float* grid = (const float*)d_in[1];
    const float* W    = (const float*)d_in[2];
    float* out        = (float*)d_out;
    int n = in_sizes[0];

    int n4 = n >> 2;
    int blocks = NBLOCKS;
    int maxBlocks = (n4 + NTHREADS - 1) / NTHREADS;
    if (maxBlocks < 1) maxBlocks = 1;
    if (blocks > maxBlocks) blocks = maxBlocks;

    bspline_actf_kernel<<<blocks, NTHREADS>>>(x, grid, W, out, n);
}